// round 11
// baseline (speedup 1.0000x reference)
#include <cuda_runtime.h>
#include <cuda_bf16.h>
#include <math.h>
#include <stdint.h>
#include <string.h>

// ---------------- problem dims ----------------
#define DD 384
#define NMAX 16384
#define MMAX 6272
#define NSPL 3
#define BATCHMAX 8
#define K4SPL 32
#define K4CH (NMAX / K4SPL)     // 512
#define NCAND (K4SPL * 9)       // 288

// ---------------- K2 tiling ----------------
#define MT 128
#define NTT 128
#define BK 64
#define MBLK (MMAX / MT)        // 49
#define NTILES (NMAX / NTT)     // 128
#define CH64 (DD / BK)          // 6
#define A_BYTES 16384
#define B_BYTES 16384
#define STAGE (A_BYTES + B_BYTES)   // 32768
#define SRED_V 128
#define SRED_I 4224
#define SM_STG 8448
#define SMEM_TOTAL (SM_STG + 3 * STAGE)   // 106752
#define FINF 3.4e38f
#define IINF 0x7fffffff

// quantization: Q = round(x/DELTA), |Q| <= 32639, Q = 256h + l
#define QSCALE 4080.0f                       // 1/DELTA = 32640/8
#define QD2 (6.007304e-8f)                   // DELTA^2
#define QC1 (131072.0f * QD2)                // 2*65536*DELTA^2
#define QC2 (512.0f * QD2)                   // 2*256*DELTA^2

// ---------------- device scratch ----------------
__device__ float g_b2[NMAX];
__device__ float g_a2[MMAX];
__device__ float g_t3v[NSPL * MMAX * 3];
__device__ int   g_t3i[NSPL * MMAX * 3];
__device__ float g_rowd[MMAX];
__device__ int   g_rowarg[MMAX];
__device__ float g_score[BATCHMAX];
__device__ int   g_mp[BATCHMAX];
__device__ int   g_nn[BATCHMAX];
__device__ float g_knn_v[BATCHMAX * NCAND];
__device__ int   g_knn_i[BATCHMAX * NCAND];

// fragment-ordered int8 staging (hi/lo planes)
// A: [chunk64][mblock][kstep(2)][plane(2)][sub16(8)][lane(32)][16B]  -> 16KB / (c,mb)
// B: [chunk64][ntile ][kstep(2)][plane(2)][sub8(16)][lane(32)][8B]   -> 16KB / (c,t)
__device__ unsigned char g_SaI[(size_t)CH64 * MBLK * 16384];
__device__ unsigned char g_ScI[(size_t)CH64 * NTILES * 16384];

// ---------------- helpers ----------------
__device__ __forceinline__ uint32_t smem_u32(const void* p) {
    uint32_t a;
    asm("{ .reg .u64 t; cvta.to.shared.u64 t, %1; cvt.u32.u64 %0, t; }" : "=r"(a) : "l"(p));
    return a;
}
__device__ __forceinline__ void mbar_init(uint32_t a, uint32_t cnt) {
    asm volatile("mbarrier.init.shared.b64 [%0], %1;" :: "r"(a), "r"(cnt) : "memory");
}
__device__ __forceinline__ void mbar_expect_tx(uint32_t a, uint32_t bytes) {
    asm volatile("mbarrier.arrive.expect_tx.shared.b64 _, [%0], %1;"
                 :: "r"(a), "r"(bytes) : "memory");
}
__device__ __forceinline__ void mbar_wait(uint32_t a, uint32_t parity) {
    asm volatile(
        "{\n\t.reg .pred P1;\n\t"
        "W_%=:\n\t"
        "mbarrier.try_wait.parity.acquire.cta.shared::cta.b64 P1, [%0], %1, 0x989680;\n\t"
        "@P1 bra.uni WD_%=;\n\t"
        "bra.uni W_%=;\n\t"
        "WD_%=:\n\t}"
        :: "r"(a), "r"(parity) : "memory");
}
__device__ __forceinline__ void bulk_g2s(uint32_t dst, const void* src, uint32_t bytes,
                                         uint32_t mbar) {
    asm volatile(
        "cp.async.bulk.shared::cta.global.mbarrier::complete_tx::bytes [%0], [%1], %2, [%3];"
        :: "r"(dst), "l"(__cvta_generic_to_global(src)), "r"(bytes), "r"(mbar) : "memory");
}
__device__ __forceinline__ void lds128(uint32_t* r, uint32_t a) {
    asm volatile("ld.shared.v4.b32 {%0,%1,%2,%3}, [%4];"
                 : "=r"(r[0]), "=r"(r[1]), "=r"(r[2]), "=r"(r[3]) : "r"(a));
}
__device__ __forceinline__ void lds64(uint32_t* r, uint32_t a) {
    asm volatile("ld.shared.v2.b32 {%0,%1}, [%2];" : "=r"(r[0]), "=r"(r[1]) : "r"(a));
}
__device__ __forceinline__ void mma_s8(int* c, const uint32_t* a, uint32_t b0, uint32_t b1) {
    asm volatile(
        "mma.sync.aligned.m16n8k32.row.col.s32.s8.s8.s32 "
        "{%0,%1,%2,%3}, {%4,%5,%6,%7}, {%8,%9}, {%0,%1,%2,%3};"
        : "+r"(c[0]), "+r"(c[1]), "+r"(c[2]), "+r"(c[3])
        : "r"(a[0]), "r"(a[1]), "r"(a[2]), "r"(a[3]), "r"(b0), "r"(b1));
}

__device__ __forceinline__ void quant1(float x, int& h, int& l) {
    float q = rintf(x * QSCALE);
    q = fminf(fmaxf(q, -32640.0f), 32639.0f);
    int Q = (int)q;
    h = (Q + 128) >> 8;
    l = Q - (h << 8);
}

// top-2 insert with lower-index tiebreak
__device__ __forceinline__ void ins2(float x, int ix, float& v1, int& i1, float& v2, int& i2) {
    if (x < v1 || (x == v1 && ix < i1)) { v2 = v1; i2 = i1; v1 = x; i1 = ix; }
    else if (x < v2 || (x == v2 && ix < i2)) { v2 = x; i2 = ix; }
}

// ---------------- K0: fp32 -> int8 (h,l) fragment-ordered staging ----------------
__global__ void k0_stage(const float* __restrict__ A, const float* __restrict__ C,
                         int M, int N)
{
    int totA = M * 96;
    int totC = N * 96;
    int idx = blockIdx.x * blockDim.x + threadIdx.x;
    if (idx >= totA + totC) return;
    const float* src;
    int r, w;
    bool isA;
    if (idx < totA) {
        r = idx / 96; w = idx % 96;
        src = A + (size_t)r * DD + w * 4;
        isA = true;
    } else {
        int i2 = idx - totA;
        r = i2 / 96; w = i2 % 96;
        src = C + (size_t)r * DD + w * 4;
        isA = false;
    }
    float4 x = *(const float4*)src;
    float xs[4] = {x.x, x.y, x.z, x.w};
    int h[4], l[4];
#pragma unroll
    for (int i = 0; i < 4; i++) quant1(xs[i], h[i], l[i]);
    uint32_t hword = (uint32_t)(h[0] & 255) | ((uint32_t)(h[1] & 255) << 8) |
                     ((uint32_t)(h[2] & 255) << 16) | ((uint32_t)(h[3] & 255) << 24);
    uint32_t lword = (uint32_t)(l[0] & 255) | ((uint32_t)(l[1] & 255) << 8) |
                     ((uint32_t)(l[2] & 255) << 16) | ((uint32_t)(l[3] & 255) << 24);

    int dd = w * 4;
    int c = dd >> 6;
    int kstep = (dd >> 5) & 1;
    int kk = dd & 31;
    if (isA) {
        int mb = r >> 7, rloc = r & 127;
        int sub = rloc >> 4, frow = rloc & 15;
        int lane = ((frow & 7) << 2) | ((kk & 15) >> 2);
        int reg = (frow >> 3) | ((kk >> 4) << 1);
        size_t base = ((size_t)(c * MBLK + mb) << 14) + ((size_t)kstep << 13);
        uint32_t off = (uint32_t)(sub << 9) + (uint32_t)(lane << 4) + (uint32_t)(reg << 2);
        *(uint32_t*)(g_SaI + base + off) = hword;
        *(uint32_t*)(g_SaI + base + 4096 + off) = lword;
    } else {
        int nt = r >> 7;
        int sub = (r & 127) >> 3;
        int lane = ((r & 7) << 2) | ((kk & 15) >> 2);
        int reg = (kk >> 4) & 1;
        size_t base = ((size_t)(c * NTILES + nt) << 14) + ((size_t)kstep << 13);
        uint32_t off = (uint32_t)(sub << 8) + (uint32_t)(lane << 3) + (uint32_t)(reg << 2);
        *(uint32_t*)(g_ScI + base + off) = hword;
        *(uint32_t*)(g_ScI + base + 4096 + off) = lword;
    }
}

// ---------------- K1: squared norms ----------------
__global__ void k1_norms(const float* __restrict__ A, const float* __restrict__ C,
                         int M, int N)
{
    int warp = (blockIdx.x * blockDim.x + threadIdx.x) >> 5;
    int lane = threadIdx.x & 31;
    int total = M + N;
    if (warp >= total) return;
    const float* src = (warp < N) ? (C + (size_t)warp * DD)
                                  : (A + (size_t)(warp - N) * DD);
    const float4* p = (const float4*)src;
    float s = 0.f;
    for (int j = lane; j < DD / 4; j += 32) {
        float4 v = p[j];
        s += v.x * v.x + v.y * v.y + v.z * v.z + v.w * v.w;
    }
#pragma unroll
    for (int off = 16; off; off >>= 1) s += __shfl_xor_sync(0xffffffffu, s, off);
    if (lane == 0) {
        if (warp < N) g_b2[warp] = s;
        else          g_a2[warp - N] = s;
    }
}

// ---------------- K2: int8x3 distance-min GEMM with top-2 ----------------
__device__ __forceinline__ void issue_chunk(uint32_t sb, int kc, int t0, int mb)
{
    int s = kc % 3;
    int tile = t0 + kc / CH64;
    int c = kc % CH64;
    uint32_t mb_addr = sb + (uint32_t)s * 8;
    uint32_t dst = sb + SM_STG + (uint32_t)s * STAGE;
    const unsigned char* asrc = g_SaI + ((size_t)(c * MBLK + mb) << 14);
    const unsigned char* bsrc = g_ScI + ((size_t)(c * NTILES + tile) << 14);
    mbar_expect_tx(mb_addr, STAGE);
    bulk_g2s(dst, asrc, A_BYTES, mb_addr);
    bulk_g2s(dst + A_BYTES, bsrc, B_BYTES, mb_addr);
}

__global__ void __launch_bounds__(256, 1)
k2_mm(int M)
{
    extern __shared__ char smem[];
    const uint32_t sb = smem_u32(smem);
    const int tid = threadIdx.x;
    const int wid = tid >> 5, lane = tid & 31;
    const int tg = lane & 3, g = lane >> 2;
    const int wm = wid >> 2, wn = wid & 3;
    const int row0 = blockIdx.x * MT;
    const int mb = blockIdx.x;
    const int split = blockIdx.y;
    const int t0 = (split * NTILES) / NSPL;
    const int t1 = ((split + 1) * NTILES) / NSPL;
    const int total = (t1 - t0) * CH64;

    if (tid == 0) {
        mbar_init(sb + 0, 1);
        mbar_init(sb + 8, 1);
        mbar_init(sb + 16, 1);
    }
    __syncthreads();

    float runv1[8], runv2[8];
    int   runi1[8], runi2[8];
#pragma unroll
    for (int s = 0; s < 8; s++) {
        runv1[s] = FINF; runv2[s] = FINF; runi1[s] = IINF; runi2[s] = IINF;
    }

    int hh[4][4][4];   // [mt][nt][4]
    int mm[4][4][4];

    if (tid == 0) {
        issue_chunk(sb, 0, t0, mb);
        issue_chunk(sb, 1, t0, mb);
    }

    for (int kc = 0; kc < total; kc++) {
        const int s = kc % 3;
        const int tile = t0 + kc / CH64;
        const int c = kc % CH64;

        if (tid == 0 && kc + 2 < total) issue_chunk(sb, kc + 2, t0, mb);

        mbar_wait(sb + (uint32_t)s * 8, (kc / 3) & 1);

        if (c == 0) {
#pragma unroll
            for (int mt = 0; mt < 4; mt++)
#pragma unroll
                for (int nt = 0; nt < 4; nt++)
#pragma unroll
                    for (int q = 0; q < 4; q++) { hh[mt][nt][q] = 0; mm[mt][nt][q] = 0; }
        }

        const uint32_t stg = sb + SM_STG + (uint32_t)s * STAGE;
#pragma unroll
        for (int ks = 0; ks < 2; ks++) {
            const uint32_t abase = stg + (uint32_t)(ks << 13) + (uint32_t)(lane << 4);
            const uint32_t bbase = stg + A_BYTES + (uint32_t)(ks << 13) + (uint32_t)(lane << 3);
            uint32_t ah[4][4], al[4][4];
#pragma unroll
            for (int mt = 0; mt < 4; mt++) {
                uint32_t ao = abase + (uint32_t)((wm * 4 + mt) << 9);
                lds128(ah[mt], ao);
                lds128(al[mt], ao + 4096);
            }
            uint32_t bh[4][2], bl[4][2];
#pragma unroll
            for (int nt = 0; nt < 4; nt++) {
                uint32_t bo = bbase + (uint32_t)((wn * 4 + nt) << 8);
                lds64(bh[nt], bo);
                lds64(bl[nt], bo + 4096);
            }
#pragma unroll
            for (int nt = 0; nt < 4; nt++) {
#pragma unroll
                for (int mt = 0; mt < 4; mt++) {
                    mma_s8(hh[mt][nt], ah[mt], bh[nt][0], bh[nt][1]);
                    mma_s8(mm[mt][nt], ah[mt], bl[nt][0], bl[nt][1]);
                    mma_s8(mm[mt][nt], al[mt], bh[nt][0], bh[nt][1]);
                }
            }
        }

        if (c == CH64 - 1) {
            const int n0t = tile * NTT;
#pragma unroll
            for (int nt = 0; nt < 4; nt++) {
                int nl = wn * 32 + nt * 8 + tg * 2;
                float b20 = __ldg(&g_b2[n0t + nl]);
                float b21 = __ldg(&g_b2[n0t + nl + 1]);
                int ng0 = n0t + nl, ng1 = ng0 + 1;
#pragma unroll
                for (int mt = 0; mt < 4; mt++) {
                    float d00 = fmaf(-QC1, (float)hh[mt][nt][0], fmaf(-QC2, (float)mm[mt][nt][0], b20));
                    float d01 = fmaf(-QC1, (float)hh[mt][nt][1], fmaf(-QC2, (float)mm[mt][nt][1], b21));
                    float d10 = fmaf(-QC1, (float)hh[mt][nt][2], fmaf(-QC2, (float)mm[mt][nt][2], b20));
                    float d11 = fmaf(-QC1, (float)hh[mt][nt][3], fmaf(-QC2, (float)mm[mt][nt][3], b21));
                    int s0 = mt * 2, s1 = mt * 2 + 1;
                    ins2(d00, ng0, runv1[s0], runi1[s0], runv2[s0], runi2[s0]);
                    ins2(d01, ng1, runv1[s0], runi1[s0], runv2[s0], runi2[s0]);
                    ins2(d10, ng0, runv1[s1], runi1[s1], runv2[s1], runi2[s1]);
                    ins2(d11, ng1, runv1[s1], runi1[s1], runv2[s1], runi2[s1]);
                }
            }
        }
        __syncthreads();
    }

    // quad merge (lanes sharing rows differ in tg)
    float* sred_v = (float*)(smem + SRED_V);
    int*   sred_i = (int*)(smem + SRED_I);
#pragma unroll
    for (int s = 0; s < 8; s++) {
        float v1 = runv1[s], v2 = runv2[s];
        int i1 = runi1[s], i2 = runi2[s];
#pragma unroll
        for (int off = 1; off <= 2; off <<= 1) {
            float w1 = __shfl_xor_sync(0xffffffffu, v1, off);
            float w2 = __shfl_xor_sync(0xffffffffu, v2, off);
            int j1 = __shfl_xor_sync(0xffffffffu, i1, off);
            int j2 = __shfl_xor_sync(0xffffffffu, i2, off);
            ins2(w1, j1, v1, i1, v2, i2);
            ins2(w2, j2, v1, i1, v2, i2);
        }
        if (tg == 0) {
            int rloc = wm * 64 + (s >> 1) * 16 + (s & 1) * 8 + g;
            sred_v[(wn * 128 + rloc) * 2 + 0] = v1;
            sred_v[(wn * 128 + rloc) * 2 + 1] = v2;
            sred_i[(wn * 128 + rloc) * 2 + 0] = i1;
            sred_i[(wn * 128 + rloc) * 2 + 1] = i2;
        }
    }
    __syncthreads();
    if (tid < 128) {
        int row = tid;
        float v[3] = {FINF, FINF, FINF};
        int id[3] = {IINF, IINF, IINF};
#pragma unroll
        for (int w = 0; w < 4; w++) {
#pragma unroll
            for (int j = 0; j < 2; j++) {
                float x = sred_v[(w * 128 + row) * 2 + j];
                int ix = sred_i[(w * 128 + row) * 2 + j];
                if (x < v[0] || (x == v[0] && ix < id[0])) {
                    v[2] = v[1]; id[2] = id[1]; v[1] = v[0]; id[1] = id[0]; v[0] = x; id[0] = ix;
                } else if (x < v[1] || (x == v[1] && ix < id[1])) {
                    v[2] = v[1]; id[2] = id[1]; v[1] = x; id[1] = ix;
                } else if (x < v[2] || (x == v[2] && ix < id[2])) {
                    v[2] = x; id[2] = ix;
                }
            }
        }
        size_t o = ((size_t)split * MMAX + row0 + row) * 3;
#pragma unroll
        for (int k = 0; k < 3; k++) { g_t3v[o + k] = v[k]; g_t3i[o + k] = id[k]; }
    }
}

// ---------------- K3a: exact fp32 refine of top-3x3 candidates per row ----------------
__global__ void k3a_refine(const float* __restrict__ A, const float* __restrict__ C, int M)
{
    int r = blockIdx.x * 8 + (threadIdx.x >> 5);
    int lane = threadIdx.x & 31;
    if (r >= M) return;
    float a_reg[12];
#pragma unroll
    for (int j = 0; j < 12; j++) a_reg[j] = A[(size_t)r * DD + j * 32 + lane];
    float a2 = g_a2[r];
    float bestv = FINF;
    int besti = IINF;
#pragma unroll
    for (int s = 0; s < NSPL; s++) {
#pragma unroll
        for (int k = 0; k < 3; k++) {
            int n = g_t3i[((size_t)s * MMAX + r) * 3 + k];
            const float* cr = C + (size_t)n * DD;
            float dot = 0.f;
#pragma unroll
            for (int j = 0; j < 12; j++) dot = fmaf(a_reg[j], cr[j * 32 + lane], dot);
#pragma unroll
            for (int off = 16; off; off >>= 1) dot += __shfl_xor_sync(0xffffffffu, dot, off);
            float d = a2 + g_b2[n] - 2.f * dot;
            if (d < bestv || (d == bestv && n < besti)) { bestv = d; besti = n; }
        }
    }
    if (lane == 0) { g_rowd[r] = bestv; g_rowarg[r] = besti; }
}

// ---------------- K3b: patch scores + per-batch argmax ----------------
__global__ void k3b_scores(int P)
{
    int b = blockIdx.x;
    int tid = threadIdx.x;
    float bestv = -1.f;
    int bestm = IINF, bestnn = 0;
    for (int p = tid; p < P; p += blockDim.x) {
        int m = b * P + p;
        float sc = sqrtf(fmaxf(g_rowd[m], 0.f));
        if (sc > bestv || (sc == bestv && m < bestm)) { bestv = sc; bestm = m; bestnn = g_rowarg[m]; }
    }
    __shared__ float sv[256];
    __shared__ int sm_[256];
    __shared__ int sn[256];
    sv[tid] = bestv; sm_[tid] = bestm; sn[tid] = bestnn;
    __syncthreads();
    for (int off = 128; off; off >>= 1) {
        if (tid < off) {
            if (sv[tid + off] > sv[tid] ||
                (sv[tid + off] == sv[tid] && sm_[tid + off] < sm_[tid])) {
                sv[tid] = sv[tid + off]; sm_[tid] = sm_[tid + off]; sn[tid] = sn[tid + off];
            }
        }
        __syncthreads();
    }
    if (tid == 0) { g_score[b] = sv[0]; g_mp[b] = sm_[0]; g_nn[b] = sn[0]; }
}

// ---------------- K4: per (batch, split-of-32) local 9-NN ----------------
__global__ void k4_knn(const float* __restrict__ C, int N)
{
    int sp = blockIdx.x;
    int b = blockIdx.y;
    int tid = threadIdx.x;
    __shared__ __align__(16) float q[DD];
    __shared__ float dv[K4CH];
    __shared__ float rv[256];
    __shared__ int   rc[256];

    int nn = g_nn[b];
    for (int j = tid; j < DD; j += 256) q[j] = C[(size_t)nn * DD + j];
    __syncthreads();
    float qn = g_b2[nn];
    int n0 = sp * K4CH;
    const float4* pq = (const float4*)q;
    for (int c = tid; c < K4CH; c += 256) {
        int n = n0 + c;
        const float4* p = (const float4*)(C + (size_t)n * DD);
        float dot = 0.f;
#pragma unroll 8
        for (int j = 0; j < DD / 4; j++) {
            float4 a = p[j], bq = pq[j];
            dot += a.x * bq.x + a.y * bq.y + a.z * bq.z + a.w * bq.w;
        }
        dv[c] = fmaxf(qn + g_b2[n] - 2.f * dot, 0.f);
    }
    __syncthreads();

    for (int k = 0; k < 9; k++) {
        float v = FINF;
        int ci = IINF;
        for (int c = tid; c < K4CH; c += 256) {
            float cv = dv[c];
            if (cv < v || (cv == v && c < ci)) { v = cv; ci = c; }
        }
        rv[tid] = v; rc[tid] = ci;
        __syncthreads();
        for (int off = 128; off; off >>= 1) {
            if (tid < off) {
                if (rv[tid + off] < rv[tid] ||
                    (rv[tid + off] == rv[tid] && rc[tid + off] < rc[tid])) {
                    rv[tid] = rv[tid + off]; rc[tid] = rc[tid + off];
                }
            }
            __syncthreads();
        }
        if (tid == 0) {
            int o = (b * K4SPL + sp) * 9 + k;
            g_knn_v[o] = rv[0];
            g_knn_i[o] = n0 + rc[0];
            dv[rc[0]] = FINF;
        }
        __syncthreads();
    }
}

// ---------------- K5: merge candidates, d_sup, softmax weight ----------------
__global__ void k5_final(const float* __restrict__ A, const float* __restrict__ C,
                         float* __restrict__ out)
{
    int b = blockIdx.x;
    int lane = threadIdx.x;
    float lv[9];
    int ln[9];
#pragma unroll
    for (int t = 0; t < 9; t++) {
        int i = lane + 32 * t;
        lv[t] = g_knn_v[b * NCAND + i];
        ln[t] = g_knn_i[b * NCAND + i];
    }
    int sup[9];
    for (int k = 0; k < 9; k++) {
        float v = FINF;
        int nix = IINF;
#pragma unroll
        for (int t = 0; t < 9; t++)
            if (lv[t] < v || (lv[t] == v && ln[t] < nix)) { v = lv[t]; nix = ln[t]; }
#pragma unroll
        for (int off = 16; off; off >>= 1) {
            float ov = __shfl_xor_sync(0xffffffffu, v, off);
            int   oi = __shfl_xor_sync(0xffffffffu, nix, off);
            if (ov < v || (ov == v && oi < nix)) { v = ov; nix = oi; }
        }
        sup[k] = nix;
#pragma unroll
        for (int t = 0; t < 9; t++)
            if (ln[t] == nix) lv[t] = FINF;
    }

    int mp = g_mp[b];
    float a2m = g_a2[mp];
    const float4* fq = (const float4*)(A + (size_t)mp * DD);
    float dsup[9];
    for (int k = 0; k < 9; k++) {
        const float4* fc = (const float4*)(C + (size_t)sup[k] * DD);
        float dot = 0.f;
        for (int j = lane; j < DD / 4; j += 32) {
            float4 x = fq[j], y = fc[j];
            dot += x.x * y.x + x.y * y.y + x.z * y.z + x.w * y.w;
        }
#pragma unroll
        for (int off = 16; off; off >>= 1) dot += __shfl_xor_sync(0xffffffffu, dot, off);
        dsup[k] = sqrtf(fmaxf(a2m + g_b2[sup[k]] - 2.f * dot, 0.f));
    }
    float mx = dsup[0];
#pragma unroll
    for (int k = 1; k < 9; k++) mx = fmaxf(mx, dsup[k]);
    float s = 0.f;
#pragma unroll
    for (int k = 0; k < 9; k++) s += expf(dsup[k] - mx);
    float w = 1.f - expf(dsup[0] - mx) / s;
    if (lane == 0) out[b] = w * g_score[b];
}

// ---------------- launch ----------------
extern "C" void kernel_launch(void* const* d_in, const int* in_sizes, int n_in,
                              void* d_out, int out_size)
{
    const float* A = (const float*)d_in[0];  // embedding [M, 384]
    const float* C = (const float*)d_in[1];  // coreset   [N, 384]
    float* out = (float*)d_out;

    int M = in_sizes[0] / DD;   // 6272
    int N = in_sizes[1] / DD;   // 16384
    int B = out_size;           // 8
    int P = M / B;              // 784

    {   // K0: quantize + fragment-ordered staging
        int tot = (M + N) * 96;
        int blocks = (tot + 255) / 256;
        k0_stage<<<blocks, 256>>>(A, C, M, N);
    }
    {   // K1: norms
        int warps = M + N;
        int blocks = (warps * 32 + 255) / 256;
        k1_norms<<<blocks, 256>>>(A, C, M, N);
    }
    {   // K2: int8x3 distance-min GEMM
        cudaFuncSetAttribute(k2_mm, cudaFuncAttributeMaxDynamicSharedMemorySize, SMEM_TOTAL);
        dim3 grid(M / MT, NSPL);
        k2_mm<<<grid, 256, SMEM_TOTAL>>>(M);
    }
    k3a_refine<<<M / 8, 256>>>(A, C, M);
    k3b_scores<<<B, 256>>>(P);
    {
        dim3 grid(K4SPL, B);
        k4_knn<<<grid, 256>>>(C, N);
    }
    k5_final<<<B, 32>>>(A, C, out);
}

// round 13
// speedup vs baseline: 4.0431x; 4.0431x over previous
#include <cuda_runtime.h>
#include <cuda_bf16.h>
#include <math.h>
#include <stdint.h>
#include <string.h>

// ---------------- problem dims ----------------
#define DD 384
#define NMAX 16384
#define MMAX 6272
#define NSPL 3
#define BATCHMAX 8
#define K4SPL 32
#define K4CH (NMAX / K4SPL)     // 512
#define NCAND (K4SPL * 9)       // 288

// ---------------- K2 tiling ----------------
#define MT 128
#define NT 256
#define NTILES (NMAX / NT)      // 64
#define CH64 (DD / 64)          // 6 chunks of 64 K-values
#define A_BYTES (MT * 128)      // 16384 (hi plane only)
#define B_BYTES (NT * 128)      // 32768
#define STAGE (A_BYTES + B_BYTES)   // 49152
#define SM_STG 6144
#define SMEM_TOTAL (SM_STG + 3 * STAGE)   // 153600
#define SRED_V 128
#define SRED_I 4224
#define FINF 3.4e38f
#define IINF 0x7fffffff

// ---------------- device scratch ----------------
__device__ float g_b2[NMAX];
__device__ float g_a2[MMAX];
__device__ float g_t3v[NSPL * MMAX * 3];
__device__ int   g_t3i[NSPL * MMAX * 3];
__device__ float g_rowd[MMAX];
__device__ int   g_rowarg[MMAX];
__device__ float g_score[BATCHMAX];
__device__ int   g_mp[BATCHMAX];
__device__ int   g_nn[BATCHMAX];
__device__ float g_knn_v[BATCHMAX * NCAND];
__device__ int   g_knn_i[BATCHMAX * NCAND];

// chunk-planar, SW128-preswizzled bf16-hi staging
// layout: [chunk64][row][128B]; 128B row = 64 bf16 covering K [64c, 64c+64)
__device__ unsigned char g_Sa[(size_t)CH64 * MMAX * 128];
__device__ unsigned char g_Sc[(size_t)CH64 * NMAX * 128];

// ---------------- helpers ----------------
__device__ __forceinline__ uint32_t smem_u32(const void* p) {
    uint32_t a;
    asm("{ .reg .u64 t; cvta.to.shared.u64 t, %1; cvt.u32.u64 %0, t; }" : "=r"(a) : "l"(p));
    return a;
}
__device__ __forceinline__ void mbar_init(uint32_t a, uint32_t cnt) {
    asm volatile("mbarrier.init.shared.b64 [%0], %1;" :: "r"(a), "r"(cnt) : "memory");
}
__device__ __forceinline__ void mbar_expect_tx(uint32_t a, uint32_t bytes) {
    asm volatile("mbarrier.arrive.expect_tx.shared.b64 _, [%0], %1;"
                 :: "r"(a), "r"(bytes) : "memory");
}
__device__ __forceinline__ void mbar_wait(uint32_t a, uint32_t parity) {
    asm volatile(
        "{\n\t.reg .pred P1;\n\t"
        "W_%=:\n\t"
        "mbarrier.try_wait.parity.acquire.cta.shared::cta.b64 P1, [%0], %1, 0x989680;\n\t"
        "@P1 bra.uni WD_%=;\n\t"
        "bra.uni W_%=;\n\t"
        "WD_%=:\n\t}"
        :: "r"(a), "r"(parity) : "memory");
}
__device__ __forceinline__ void bulk_g2s(uint32_t dst, const void* src, uint32_t bytes,
                                         uint32_t mbar) {
    asm volatile(
        "cp.async.bulk.shared::cta.global.mbarrier::complete_tx::bytes [%0], [%1], %2, [%3];"
        :: "r"(dst), "l"(__cvta_generic_to_global(src)), "r"(bytes), "r"(mbar) : "memory");
}
__device__ __forceinline__ void ldsm4(uint32_t* r, uint32_t a) {
    asm volatile("ldmatrix.sync.aligned.m8n8.x4.shared.b16 {%0,%1,%2,%3}, [%4];"
                 : "=r"(r[0]), "=r"(r[1]), "=r"(r[2]), "=r"(r[3]) : "r"(a));
}
__device__ __forceinline__ void ldsm2(uint32_t* r, uint32_t a) {
    asm volatile("ldmatrix.sync.aligned.m8n8.x2.shared.b16 {%0,%1}, [%2];"
                 : "=r"(r[0]), "=r"(r[1]) : "r"(a));
}
__device__ __forceinline__ void mma16816(float* c, const uint32_t* a, uint32_t b0, uint32_t b1) {
    asm volatile(
        "mma.sync.aligned.m16n8k16.row.col.f32.bf16.bf16.f32 "
        "{%0,%1,%2,%3}, {%4,%5,%6,%7}, {%8,%9}, {%0,%1,%2,%3};"
        : "+f"(c[0]), "+f"(c[1]), "+f"(c[2]), "+f"(c[3])
        : "r"(a[0]), "r"(a[1]), "r"(a[2]), "r"(a[3]), "r"(b0), "r"(b1));
}

// top-2 insert with lower-index tiebreak
__device__ __forceinline__ void ins2(float x, int ix, float& v1, int& i1, float& v2, int& i2) {
    if (x < v1 || (x == v1 && ix < i1)) { v2 = v1; i2 = i1; v1 = x; i1 = ix; }
    else if (x < v2 || (x == v2 && ix < i2)) { v2 = x; i2 = ix; }
}

// ---------------- K0: fp32 -> bf16-hi staged (chunk-planar, pre-swizzled) ----------------
__global__ void k0_stage(const float* __restrict__ A, const float* __restrict__ C,
                         int M, int N)
{
    int totA = M * 96;
    int totC = N * 96;
    int idx = blockIdx.x * blockDim.x + threadIdx.x;
    if (idx >= totA + totC) return;
    const float* src;
    unsigned char* dstbase;
    int r, w, rows;
    if (idx < totA) {
        r = idx / 96; w = idx % 96;
        src = A + (size_t)r * DD + w * 4;
        dstbase = g_Sa; rows = M;
    } else {
        int i2 = idx - totA;
        r = i2 / 96; w = i2 % 96;
        src = C + (size_t)r * DD + w * 4;
        dstbase = g_Sc; rows = N;
    }
    float4 x = *(const float4*)src;
    float xs[4] = {x.x, x.y, x.z, x.w};
    unsigned short hs[4];
#pragma unroll
    for (int i = 0; i < 4; i++) {
        __nv_bfloat16 h = __float2bfloat16(xs[i]);
        memcpy(&hs[i], &h, 2);
    }
    uint2 ph;
    ph.x = (uint32_t)hs[0] | ((uint32_t)hs[1] << 16);
    ph.y = (uint32_t)hs[2] | ((uint32_t)hs[3] << 16);

    int dd = w * 4;                 // element index in row
    int c = dd >> 6;                // chunk64
    int kk = dd & 63;               // element within chunk
    int j = kk >> 3;                // 16B group (0..7)
    int hj = (kk >> 2) & 1;         // 8B half within group
    int r7 = r & 7;
    size_t base = ((size_t)c * rows + (size_t)(r & ~7)) * 128;
    uint32_t off = (uint32_t)r7 * 128 + ((uint32_t)(j ^ r7) << 4) + (uint32_t)hj * 8;
    *(uint2*)(dstbase + base + off) = ph;
}

// ---------------- K1: squared norms ----------------
__global__ void k1_norms(const float* __restrict__ A, const float* __restrict__ C,
                         int M, int N)
{
    int warp = (blockIdx.x * blockDim.x + threadIdx.x) >> 5;
    int lane = threadIdx.x & 31;
    int total = M + N;
    if (warp >= total) return;
    const float* src = (warp < N) ? (C + (size_t)warp * DD)
                                  : (A + (size_t)(warp - N) * DD);
    const float4* p = (const float4*)src;
    float s = 0.f;
    for (int j = lane; j < DD / 4; j += 32) {
        float4 v = p[j];
        s += v.x * v.x + v.y * v.y + v.z * v.z + v.w * v.w;
    }
#pragma unroll
    for (int off = 16; off; off >>= 1) s += __shfl_xor_sync(0xffffffffu, s, off);
    if (lane == 0) {
        if (warp < N) g_b2[warp] = s;
        else          g_a2[warp - N] = s;
    }
}

// ---------------- K2: bulk-DMA + ldmatrix + single-pass bf16 HMMA, top-2 ----------------
__device__ __forceinline__ void issue_chunk(uint32_t sb, int kc, int t0, int row0, int M)
{
    int s = kc % 3;
    int tile = t0 + kc / CH64;
    int c = kc % CH64;
    uint32_t mb = sb + (uint32_t)s * 8;
    uint32_t dst = sb + SM_STG + (uint32_t)s * STAGE;
    const unsigned char* asrc = g_Sa + ((size_t)c * M + row0) * 128;
    const unsigned char* bsrc = g_Sc + ((size_t)c * NMAX + (size_t)tile * NT) * 128;
    mbar_expect_tx(mb, STAGE);
    bulk_g2s(dst, asrc, A_BYTES, mb);
    bulk_g2s(dst + A_BYTES, bsrc, B_BYTES, mb);
}

__global__ void __launch_bounds__(256, 1)
k2_mm(int M)
{
    extern __shared__ char smem[];
    const uint32_t sb = smem_u32(smem);
    const int tid = threadIdx.x;
    const int wid = tid >> 5, lane = tid & 31;
    const int tg = lane & 3, g = lane >> 2;
    const int wm = wid >> 2, wn = wid & 3;
    const int row0 = blockIdx.x * MT;
    const int split = blockIdx.y;
    const int t0 = (split * NTILES) / NSPL;
    const int t1 = ((split + 1) * NTILES) / NSPL;
    const int total = (t1 - t0) * CH64;

    // ldmatrix per-lane address components
    const uint32_t r15 = lane & 15;
    const uint32_t r7a = r15 & 7;
    const uint32_t parta = (lane >> 4) & 1;
    const uint32_t rb8 = lane & 7;
    const uint32_t pb = (lane >> 3) & 1;

    if (tid == 0) {
        mbar_init(sb + 0, 1);
        mbar_init(sb + 8, 1);
        mbar_init(sb + 16, 1);
    }
    __syncthreads();

    float runv1[8], runv2[8];
    int   runi1[8], runi2[8];
#pragma unroll
    for (int s = 0; s < 8; s++) {
        runv1[s] = FINF; runv2[s] = FINF; runi1[s] = IINF; runi2[s] = IINF;
    }

    float acc[4][8][4];

    if (tid == 0) {
        issue_chunk(sb, 0, t0, row0, M);
        issue_chunk(sb, 1, t0, row0, M);
    }

    for (int kc = 0; kc < total; kc++) {
        const int s = kc % 3;
        const int tile = t0 + kc / CH64;
        const int c = kc % CH64;

        if (tid == 0 && kc + 2 < total) issue_chunk(sb, kc + 2, t0, row0, M);

        mbar_wait(sb + (uint32_t)s * 8, (kc / 3) & 1);

        if (c == 0) {
#pragma unroll
            for (int mt = 0; mt < 4; mt++)
#pragma unroll
                for (int nt = 0; nt < 8; nt++)
#pragma unroll
                    for (int q = 0; q < 4; q++) acc[mt][nt][q] = 0.f;
        }

        const uint32_t stg = sb + SM_STG + (uint32_t)s * STAGE;
        const uint32_t stgB = stg + A_BYTES;
#pragma unroll
        for (int ks = 0; ks < 4; ks++) {
            uint32_t ah[4][4];
            const uint32_t gga = ((uint32_t)(ks * 2) + parta) ^ r7a;
#pragma unroll
            for (int mt = 0; mt < 4; mt++) {
                uint32_t arow = stg + (uint32_t)((wm * 64 + mt * 16) + r15) * 128;
                ldsm4(ah[mt], arow + (gga << 4));
            }
            const uint32_t ggb = ((uint32_t)(ks * 2) + pb) ^ rb8;
#pragma unroll
            for (int nt = 0; nt < 8; nt++) {
                uint32_t brow = stgB + (uint32_t)((wn * 64 + nt * 8) + rb8) * 128;
                uint32_t bh[2];
                ldsm2(bh, brow + (ggb << 4));
#pragma unroll
                for (int mt = 0; mt < 4; mt++)
                    mma16816(acc[mt][nt], ah[mt], bh[0], bh[1]);
            }
        }

        if (c == CH64 - 1) {
            const int n0 = tile * NT;
#pragma unroll
            for (int nt = 0; nt < 8; nt++) {
                int nl = wn * 64 + nt * 8 + tg * 2;
                float b20 = __ldg(&g_b2[n0 + nl]);
                float b21 = __ldg(&g_b2[n0 + nl + 1]);
                int ng0 = n0 + nl, ng1 = ng0 + 1;
#pragma unroll
                for (int mt = 0; mt < 4; mt++) {
                    const float* cc = acc[mt][nt];
                    float d00 = fmaf(-2.f, cc[0], b20);
                    float d01 = fmaf(-2.f, cc[1], b21);
                    float d10 = fmaf(-2.f, cc[2], b20);
                    float d11 = fmaf(-2.f, cc[3], b21);
                    int s0 = mt * 2, s1 = mt * 2 + 1;
                    ins2(d00, ng0, runv1[s0], runi1[s0], runv2[s0], runi2[s0]);
                    ins2(d01, ng1, runv1[s0], runi1[s0], runv2[s0], runi2[s0]);
                    ins2(d10, ng0, runv1[s1], runi1[s1], runv2[s1], runi2[s1]);
                    ins2(d11, ng1, runv1[s1], runi1[s1], runv2[s1], runi2[s1]);
                }
            }
        }
        __syncthreads();
    }

    // quad merge across tg lanes, then cross-warp top-3 per row
    float* sred_v = (float*)(smem + SRED_V);
    int*   sred_i = (int*)(smem + SRED_I);
#pragma unroll
    for (int s = 0; s < 8; s++) {
        float v1 = runv1[s], v2 = runv2[s];
        int i1 = runi1[s], i2 = runi2[s];
#pragma unroll
        for (int off = 1; off <= 2; off <<= 1) {
            float w1 = __shfl_xor_sync(0xffffffffu, v1, off);
            float w2 = __shfl_xor_sync(0xffffffffu, v2, off);
            int j1 = __shfl_xor_sync(0xffffffffu, i1, off);
            int j2 = __shfl_xor_sync(0xffffffffu, i2, off);
            ins2(w1, j1, v1, i1, v2, i2);
            ins2(w2, j2, v1, i1, v2, i2);
        }
        if (tg == 0) {
            int rloc = wm * 64 + (s >> 1) * 16 + (s & 1) * 8 + g;
            sred_v[(wn * 128 + rloc) * 2 + 0] = v1;
            sred_v[(wn * 128 + rloc) * 2 + 1] = v2;
            sred_i[(wn * 128 + rloc) * 2 + 0] = i1;
            sred_i[(wn * 128 + rloc) * 2 + 1] = i2;
        }
    }
    __syncthreads();
    if (tid < 128) {
        int row = tid;
        float v[3] = {FINF, FINF, FINF};
        int id[3] = {IINF, IINF, IINF};
#pragma unroll
        for (int w = 0; w < 4; w++) {
#pragma unroll
            for (int j = 0; j < 2; j++) {
                float x = sred_v[(w * 128 + row) * 2 + j];
                int ix = sred_i[(w * 128 + row) * 2 + j];
                if (x < v[0] || (x == v[0] && ix < id[0])) {
                    v[2] = v[1]; id[2] = id[1]; v[1] = v[0]; id[1] = id[0]; v[0] = x; id[0] = ix;
                } else if (x < v[1] || (x == v[1] && ix < id[1])) {
                    v[2] = v[1]; id[2] = id[1]; v[1] = x; id[1] = ix;
                } else if (x < v[2] || (x == v[2] && ix < id[2])) {
                    v[2] = x; id[2] = ix;
                }
            }
        }
        size_t o = ((size_t)split * MMAX + row0 + row) * 3;
#pragma unroll
        for (int k = 0; k < 3; k++) { g_t3v[o + k] = v[k]; g_t3i[o + k] = id[k]; }
    }
}

// ---------------- K3a: exact fp32 refine of top-3x3 candidates per row ----------------
__global__ void k3a_refine(const float* __restrict__ A, const float* __restrict__ C, int M)
{
    int r = blockIdx.x * 8 + (threadIdx.x >> 5);
    int lane = threadIdx.x & 31;
    if (r >= M) return;
    float a_reg[12];
#pragma unroll
    for (int j = 0; j < 12; j++) a_reg[j] = A[(size_t)r * DD + j * 32 + lane];
    float a2 = g_a2[r];
    float bestv = FINF;
    int besti = IINF;
#pragma unroll
    for (int s = 0; s < NSPL; s++) {
#pragma unroll
        for (int k = 0; k < 3; k++) {
            int n = g_t3i[((size_t)s * MMAX + r) * 3 + k];
            const float* cr = C + (size_t)n * DD;
            float dot = 0.f;
#pragma unroll
            for (int j = 0; j < 12; j++) dot = fmaf(a_reg[j], cr[j * 32 + lane], dot);
#pragma unroll
            for (int off = 16; off; off >>= 1) dot += __shfl_xor_sync(0xffffffffu, dot, off);
            float d = a2 + g_b2[n] - 2.f * dot;
            if (d < bestv || (d == bestv && n < besti)) { bestv = d; besti = n; }
        }
    }
    if (lane == 0) { g_rowd[r] = bestv; g_rowarg[r] = besti; }
}

// ---------------- K3b: patch scores + per-batch argmax ----------------
__global__ void k3b_scores(int P)
{
    int b = blockIdx.x;
    int tid = threadIdx.x;
    float bestv = -1.f;
    int bestm = IINF, bestnn = 0;
    for (int p = tid; p < P; p += blockDim.x) {
        int m = b * P + p;
        float sc = sqrtf(fmaxf(g_rowd[m], 0.f));
        if (sc > bestv || (sc == bestv && m < bestm)) { bestv = sc; bestm = m; bestnn = g_rowarg[m]; }
    }
    __shared__ float sv[256];
    __shared__ int sm_[256];
    __shared__ int sn[256];
    sv[tid] = bestv; sm_[tid] = bestm; sn[tid] = bestnn;
    __syncthreads();
    for (int off = 128; off; off >>= 1) {
        if (tid < off) {
            if (sv[tid + off] > sv[tid] ||
                (sv[tid + off] == sv[tid] && sm_[tid + off] < sm_[tid])) {
                sv[tid] = sv[tid + off]; sm_[tid] = sm_[tid + off]; sn[tid] = sn[tid + off];
            }
        }
        __syncthreads();
    }
    if (tid == 0) { g_score[b] = sv[0]; g_mp[b] = sm_[0]; g_nn[b] = sn[0]; }
}

// ---------------- K4: per (batch, split-of-32) local 9-NN ----------------
__global__ void k4_knn(const float* __restrict__ C, int N)
{
    int sp = blockIdx.x;
    int b = blockIdx.y;
    int tid = threadIdx.x;
    __shared__ __align__(16) float q[DD];
    __shared__ float dv[K4CH];
    __shared__ float rv[256];
    __shared__ int   rc[256];

    int nn = g_nn[b];
    for (int j = tid; j < DD; j += 256) q[j] = C[(size_t)nn * DD + j];
    __syncthreads();
    float qn = g_b2[nn];
    int n0 = sp * K4CH;
    const float4* pq = (const float4*)q;
    for (int c = tid; c < K4CH; c += 256) {
        int n = n0 + c;
        const float4* p = (const float4*)(C + (size_t)n * DD);
        float dot = 0.f;
#pragma unroll 8
        for (int j = 0; j < DD / 4; j++) {
            float4 a = p[j], bq = pq[j];
            dot += a.x * bq.x + a.y * bq.y + a.z * bq.z + a.w * bq.w;
        }
        dv[c] = fmaxf(qn + g_b2[n] - 2.f * dot, 0.f);
    }
    __syncthreads();

    for (int k = 0; k < 9; k++) {
        float v = FINF;
        int ci = IINF;
        for (int c = tid; c < K4CH; c += 256) {
            float cv = dv[c];
            if (cv < v || (cv == v && c < ci)) { v = cv; ci = c; }
        }
        rv[tid] = v; rc[tid] = ci;
        __syncthreads();
        for (int off = 128; off; off >>= 1) {
            if (tid < off) {
                if (rv[tid + off] < rv[tid] ||
                    (rv[tid + off] == rv[tid] && rc[tid + off] < rc[tid])) {
                    rv[tid] = rv[tid + off]; rc[tid] = rc[tid + off];
                }
            }
            __syncthreads();
        }
        if (tid == 0) {
            int o = (b * K4SPL + sp) * 9 + k;
            g_knn_v[o] = rv[0];
            g_knn_i[o] = n0 + rc[0];
            dv[rc[0]] = FINF;
        }
        __syncthreads();
    }
}

// ---------------- K5: merge candidates, d_sup, softmax weight ----------------
__global__ void k5_final(const float* __restrict__ A, const float* __restrict__ C,
                         float* __restrict__ out)
{
    int b = blockIdx.x;
    int lane = threadIdx.x;
    float lv[9];
    int ln[9];
#pragma unroll
    for (int t = 0; t < 9; t++) {
        int i = lane + 32 * t;
        lv[t] = g_knn_v[b * NCAND + i];
        ln[t] = g_knn_i[b * NCAND + i];
    }
    int sup[9];
    for (int k = 0; k < 9; k++) {
        float v = FINF;
        int nix = IINF;
#pragma unroll
        for (int t = 0; t < 9; t++)
            if (lv[t] < v || (lv[t] == v && ln[t] < nix)) { v = lv[t]; nix = ln[t]; }
#pragma unroll
        for (int off = 16; off; off >>= 1) {
            float ov = __shfl_xor_sync(0xffffffffu, v, off);
            int   oi = __shfl_xor_sync(0xffffffffu, nix, off);
            if (ov < v || (ov == v && oi < nix)) { v = ov; nix = oi; }
        }
        sup[k] = nix;
#pragma unroll
        for (int t = 0; t < 9; t++)
            if (ln[t] == nix) lv[t] = FINF;
    }

    int mp = g_mp[b];
    float a2m = g_a2[mp];
    const float4* fq = (const float4*)(A + (size_t)mp * DD);
    float dsup[9];
    for (int k = 0; k < 9; k++) {
        const float4* fc = (const float4*)(C + (size_t)sup[k] * DD);
        float dot = 0.f;
        for (int j = lane; j < DD / 4; j += 32) {
            float4 x = fq[j], y = fc[j];
            dot += x.x * y.x + x.y * y.y + x.z * y.z + x.w * y.w;
        }
#pragma unroll
        for (int off = 16; off; off >>= 1) dot += __shfl_xor_sync(0xffffffffu, dot, off);
        dsup[k] = sqrtf(fmaxf(a2m + g_b2[sup[k]] - 2.f * dot, 0.f));
    }
    float mx = dsup[0];
#pragma unroll
    for (int k = 1; k < 9; k++) mx = fmaxf(mx, dsup[k]);
    float s = 0.f;
#pragma unroll
    for (int k = 0; k < 9; k++) s += expf(dsup[k] - mx);
    float w = 1.f - expf(dsup[0] - mx) / s;
    if (lane == 0) out[b] = w * g_score[b];
}

// ---------------- launch ----------------
extern "C" void kernel_launch(void* const* d_in, const int* in_sizes, int n_in,
                              void* d_out, int out_size)
{
    const float* A = (const float*)d_in[0];  // embedding [M, 384]
    const float* C = (const float*)d_in[1];  // coreset   [N, 384]
    float* out = (float*)d_out;

    int M = in_sizes[0] / DD;   // 6272
    int N = in_sizes[1] / DD;   // 16384
    int B = out_size;           // 8
    int P = M / B;              // 784

    {   // K0: bf16-hi staging (chunk-planar, pre-swizzled)
        int tot = (M + N) * 96;
        int blocks = (tot + 255) / 256;
        k0_stage<<<blocks, 256>>>(A, C, M, N);
    }
    {   // K1: norms
        int warps = M + N;
        int blocks = (warps * 32 + 255) / 256;
        k1_norms<<<blocks, 256>>>(A, C, M, N);
    }
    {   // K2: single-pass bf16 HMMA distance-min GEMM (top-2 -> top-3)
        cudaFuncSetAttribute(k2_mm, cudaFuncAttributeMaxDynamicSharedMemorySize, SMEM_TOTAL);
        dim3 grid(M / MT, NSPL);
        k2_mm<<<grid, 256, SMEM_TOTAL>>>(M);
    }
    k3a_refine<<<M / 8, 256>>>(A, C, M);
    k3b_scores<<<B, 256>>>(P);
    {
        dim3 grid(K4SPL, B);
        k4_knn<<<grid, 256>>>(C, N);
    }
    k5_final<<<B, 32>>>(A, C, out);
}

// round 17
// speedup vs baseline: 4.9427x; 1.2225x over previous
#include <cuda_runtime.h>
#include <cuda_bf16.h>
#include <math.h>
#include <stdint.h>
#include <string.h>

// ---------------- problem dims ----------------
#define DD 384
#define NMAX 16384
#define MMAX 6272
#define NSPL 6
#define BATCHMAX 8
#define K4SPL 32
#define K4CH (NMAX / K4SPL)     // 512
#define NCAND (K4SPL * 9)       // 288

// ---------------- K2 tiling ----------------
#define MT 128
#define NT 128
#define NTILES (NMAX / NT)      // 128
#define CH64 (DD / 64)          // 6 chunks of 64 K-values
#define A_BYTES (MT * 128)      // 16384
#define B_BYTES (NT * 128)      // 16384
#define STAGE (A_BYTES + B_BYTES)   // 32768
#define SM_STG 6144
#define SMEM_TOTAL (SM_STG + 3 * STAGE)   // 104448
#define SRED_V 128
#define SRED_I 4224
#define FINF 3.4e38f
#define IINF 0x7fffffff

// ---------------- device scratch ----------------
__device__ float g_b2[NMAX];
__device__ float g_a2[MMAX];
__device__ float g_t3v[NSPL * MMAX * 3];
__device__ int   g_t3i[NSPL * MMAX * 3];
__device__ float g_rowd[MMAX];
__device__ int   g_rowarg[MMAX];
__device__ float g_score[BATCHMAX];
__device__ int   g_mp[BATCHMAX];
__device__ int   g_nn[BATCHMAX];
__device__ float g_knn_v[BATCHMAX * NCAND];
__device__ int   g_knn_i[BATCHMAX * NCAND];

// chunk-planar, SW128-preswizzled bf16 staging
// layout: [chunk64][row][128B]; 128B row = 64 bf16 covering K [64c, 64c+64)
__device__ unsigned char g_Sa[(size_t)CH64 * MMAX * 128];
__device__ unsigned char g_Sc[(size_t)CH64 * NMAX * 128];

// ---------------- helpers ----------------
__device__ __forceinline__ uint32_t smem_u32(const void* p) {
    uint32_t a;
    asm("{ .reg .u64 t; cvta.to.shared.u64 t, %1; cvt.u32.u64 %0, t; }" : "=r"(a) : "l"(p));
    return a;
}
__device__ __forceinline__ void mbar_init(uint32_t a, uint32_t cnt) {
    asm volatile("mbarrier.init.shared.b64 [%0], %1;" :: "r"(a), "r"(cnt) : "memory");
}
__device__ __forceinline__ void mbar_expect_tx(uint32_t a, uint32_t bytes) {
    asm volatile("mbarrier.arrive.expect_tx.shared.b64 _, [%0], %1;"
                 :: "r"(a), "r"(bytes) : "memory");
}
__device__ __forceinline__ void mbar_wait(uint32_t a, uint32_t parity) {
    asm volatile(
        "{\n\t.reg .pred P1;\n\t"
        "W_%=:\n\t"
        "mbarrier.try_wait.parity.acquire.cta.shared::cta.b64 P1, [%0], %1, 0x989680;\n\t"
        "@P1 bra.uni WD_%=;\n\t"
        "bra.uni W_%=;\n\t"
        "WD_%=:\n\t}"
        :: "r"(a), "r"(parity) : "memory");
}
__device__ __forceinline__ void bulk_g2s(uint32_t dst, const void* src, uint32_t bytes,
                                         uint32_t mbar) {
    asm volatile(
        "cp.async.bulk.shared::cta.global.mbarrier::complete_tx::bytes [%0], [%1], %2, [%3];"
        :: "r"(dst), "l"(__cvta_generic_to_global(src)), "r"(bytes), "r"(mbar) : "memory");
}
__device__ __forceinline__ void ldsm4(uint32_t* r, uint32_t a) {
    asm volatile("ldmatrix.sync.aligned.m8n8.x4.shared.b16 {%0,%1,%2,%3}, [%4];"
                 : "=r"(r[0]), "=r"(r[1]), "=r"(r[2]), "=r"(r[3]) : "r"(a));
}
__device__ __forceinline__ void mma16816(float* c, const uint32_t* a, uint32_t b0, uint32_t b1) {
    asm volatile(
        "mma.sync.aligned.m16n8k16.row.col.f32.bf16.bf16.f32 "
        "{%0,%1,%2,%3}, {%4,%5,%6,%7}, {%8,%9}, {%0,%1,%2,%3};"
        : "+f"(c[0]), "+f"(c[1]), "+f"(c[2]), "+f"(c[3])
        : "r"(a[0]), "r"(a[1]), "r"(a[2]), "r"(a[3]), "r"(b0), "r"(b1));
}

// top-2 insert with lower-index tiebreak
__device__ __forceinline__ void ins2(float x, int ix, float& v1, int& i1, float& v2, int& i2) {
    if (x < v1 || (x == v1 && ix < i1)) { v2 = v1; i2 = i1; v1 = x; i1 = ix; }
    else if (x < v2 || (x == v2 && ix < i2)) { v2 = x; i2 = ix; }
}

// ---------------- K0: fp32 -> bf16-hi staged (chunk-planar, pre-swizzled) ----------------
__global__ void k0_stage(const float* __restrict__ A, const float* __restrict__ C,
                         int M, int N)
{
    int totA = M * 96;
    int totC = N * 96;
    int idx = blockIdx.x * blockDim.x + threadIdx.x;
    if (idx >= totA + totC) return;
    const float* src;
    unsigned char* dstbase;
    int r, w, rows;
    if (idx < totA) {
        r = idx / 96; w = idx % 96;
        src = A + (size_t)r * DD + w * 4;
        dstbase = g_Sa; rows = M;
    } else {
        int i2 = idx - totA;
        r = i2 / 96; w = i2 % 96;
        src = C + (size_t)r * DD + w * 4;
        dstbase = g_Sc; rows = N;
    }
    float4 x = *(const float4*)src;
    float xs[4] = {x.x, x.y, x.z, x.w};
    unsigned short hs[4];
#pragma unroll
    for (int i = 0; i < 4; i++) {
        __nv_bfloat16 h = __float2bfloat16(xs[i]);
        memcpy(&hs[i], &h, 2);
    }
    uint2 ph;
    ph.x = (uint32_t)hs[0] | ((uint32_t)hs[1] << 16);
    ph.y = (uint32_t)hs[2] | ((uint32_t)hs[3] << 16);

    int dd = w * 4;
    int c = dd >> 6;
    int kk = dd & 63;
    int j = kk >> 3;
    int hj = (kk >> 2) & 1;
    int r7 = r & 7;
    size_t base = ((size_t)c * rows + (size_t)(r & ~7)) * 128;
    uint32_t off = (uint32_t)r7 * 128 + ((uint32_t)(j ^ r7) << 4) + (uint32_t)hj * 8;
    *(uint2*)(dstbase + base + off) = ph;
}

// ---------------- K1: squared norms ----------------
__global__ void k1_norms(const float* __restrict__ A, const float* __restrict__ C,
                         int M, int N)
{
    int warp = (blockIdx.x * blockDim.x + threadIdx.x) >> 5;
    int lane = threadIdx.x & 31;
    int total = M + N;
    if (warp >= total) return;
    const float* src = (warp < N) ? (C + (size_t)warp * DD)
                                  : (A + (size_t)(warp - N) * DD);
    const float4* p = (const float4*)src;
    float s = 0.f;
    for (int j = lane; j < DD / 4; j += 32) {
        float4 v = p[j];
        s += v.x * v.x + v.y * v.y + v.z * v.z + v.w * v.w;
    }
#pragma unroll
    for (int off = 16; off; off >>= 1) s += __shfl_xor_sync(0xffffffffu, s, off);
    if (lane == 0) {
        if (warp < N) g_b2[warp] = s;
        else          g_a2[warp - N] = s;
    }
}

// ---------------- K2: 2 CTA/SM bf16 HMMA distance-min GEMM, top-2 ----------------
__device__ __forceinline__ void issue_chunk(uint32_t sb, int kc, int t0, int row0, int M)
{
    int s = kc % 3;
    int tile = t0 + kc / CH64;
    int c = kc % CH64;
    uint32_t mb = sb + (uint32_t)s * 8;
    uint32_t dst = sb + SM_STG + (uint32_t)s * STAGE;
    const unsigned char* asrc = g_Sa + ((size_t)c * M + row0) * 128;
    const unsigned char* bsrc = g_Sc + ((size_t)c * NMAX + (size_t)tile * NT) * 128;
    mbar_expect_tx(mb, STAGE);
    bulk_g2s(dst, asrc, A_BYTES, mb);
    bulk_g2s(dst + A_BYTES, bsrc, B_BYTES, mb);
}

__global__ void __launch_bounds__(256, 2)
k2_mm(int M)
{
    extern __shared__ char smem[];
    const uint32_t sb = smem_u32(smem);
    const int tid = threadIdx.x;
    const int wid = tid >> 5, lane = tid & 31;
    const int tg = lane & 3, g = lane >> 2;
    const int wm = wid >> 2, wn = wid & 3;
    const int row0 = blockIdx.x * MT;
    const int split = blockIdx.y;
    const int t0 = (split * NTILES) / NSPL;
    const int t1 = ((split + 1) * NTILES) / NSPL;
    const int total = (t1 - t0) * CH64;

    // ldmatrix per-lane address components
    const uint32_t r15 = lane & 15;          // A rows
    const uint32_t r7a = r15 & 7;
    const uint32_t parta = (lane >> 4) & 1;  // A k-half
    const uint32_t rb8 = lane & 7;           // B rows
    const uint32_t pb = (lane >> 3) & 1;     // B k-half
    const uint32_t ntsel = (lane >> 4) & 1;  // B nt-pair select

    if (tid == 0) {
        mbar_init(sb + 0, 1);
        mbar_init(sb + 8, 1);
        mbar_init(sb + 16, 1);
    }
    __syncthreads();

    float runv1[8], runv2[8];
    int   runi1[8], runi2[8];
#pragma unroll
    for (int s = 0; s < 8; s++) {
        runv1[s] = FINF; runv2[s] = FINF; runi1[s] = IINF; runi2[s] = IINF;
    }

    float acc[4][4][4];   // [mt][nt][4]

    if (tid == 0) {
        issue_chunk(sb, 0, t0, row0, M);
        issue_chunk(sb, 1, t0, row0, M);
    }

    for (int kc = 0; kc < total; kc++) {
        const int s = kc % 3;
        const int tile = t0 + kc / CH64;
        const int c = kc % CH64;

        if (tid == 0 && kc + 2 < total) issue_chunk(sb, kc + 2, t0, row0, M);

        mbar_wait(sb + (uint32_t)s * 8, (kc / 3) & 1);

        if (c == 0) {
#pragma unroll
            for (int mt = 0; mt < 4; mt++)
#pragma unroll
                for (int nt = 0; nt < 4; nt++)
#pragma unroll
                    for (int q = 0; q < 4; q++) acc[mt][nt][q] = 0.f;
        }

        const uint32_t stg = sb + SM_STG + (uint32_t)s * STAGE;
        const uint32_t stgB = stg + A_BYTES;
#pragma unroll
        for (int ks = 0; ks < 4; ks++) {
            uint32_t ah[4][4];
            const uint32_t gga = ((uint32_t)(ks * 2) + parta) ^ r7a;
#pragma unroll
            for (int mt = 0; mt < 4; mt++) {
                uint32_t arow = stg + (uint32_t)((wm * 64 + mt * 16) + r15) * 128;
                ldsm4(ah[mt], arow + (gga << 4));
            }
            // B: one ldsm4 covers an nt-pair (lanes 16-31 take nt+1)
            const uint32_t ggb = ((uint32_t)(ks * 2) + pb) ^ rb8;
            uint32_t bf[2][4];
#pragma unroll
            for (int np = 0; np < 2; np++) {
                uint32_t brow = stgB +
                    (uint32_t)((wn * 32 + (np * 2 + ntsel) * 8) + rb8) * 128;
                ldsm4(bf[np], brow + (ggb << 4));
            }
#pragma unroll
            for (int np = 0; np < 2; np++) {
#pragma unroll
                for (int half = 0; half < 2; half++) {
                    int nt = np * 2 + half;
#pragma unroll
                    for (int mt = 0; mt < 4; mt++)
                        mma16816(acc[mt][nt], ah[mt], bf[np][half * 2], bf[np][half * 2 + 1]);
                }
            }
        }

        if (c == CH64 - 1) {
            const int n0 = tile * NT;
#pragma unroll
            for (int nt = 0; nt < 4; nt++) {
                int nl = wn * 32 + nt * 8 + tg * 2;
                float b20 = __ldg(&g_b2[n0 + nl]);
                float b21 = __ldg(&g_b2[n0 + nl + 1]);
                int ng0 = n0 + nl, ng1 = ng0 + 1;
#pragma unroll
                for (int mt = 0; mt < 4; mt++) {
                    const float* cc = acc[mt][nt];
                    float d00 = fmaf(-2.f, cc[0], b20);
                    float d01 = fmaf(-2.f, cc[1], b21);
                    float d10 = fmaf(-2.f, cc[2], b20);
                    float d11 = fmaf(-2.f, cc[3], b21);
                    int s0 = mt * 2, s1 = mt * 2 + 1;
                    ins2(d00, ng0, runv1[s0], runi1[s0], runv2[s0], runi2[s0]);
                    ins2(d01, ng1, runv1[s0], runi1[s0], runv2[s0], runi2[s0]);
                    ins2(d10, ng0, runv1[s1], runi1[s1], runv2[s1], runi2[s1]);
                    ins2(d11, ng1, runv1[s1], runi1[s1], runv2[s1], runi2[s1]);
                }
            }
        }
        __syncthreads();
    }

    // quad merge across tg lanes, then cross-warp top-3 per row
    float* sred_v = (float*)(smem + SRED_V);
    int*   sred_i = (int*)(smem + SRED_I);
#pragma unroll
    for (int s = 0; s < 8; s++) {
        float v1 = runv1[s], v2 = runv2[s];
        int i1 = runi1[s], i2 = runi2[s];
#pragma unroll
        for (int off = 1; off <= 2; off <<= 1) {
            float w1 = __shfl_xor_sync(0xffffffffu, v1, off);
            float w2 = __shfl_xor_sync(0xffffffffu, v2, off);
            int j1 = __shfl_xor_sync(0xffffffffu, i1, off);
            int j2 = __shfl_xor_sync(0xffffffffu, i2, off);
            ins2(w1, j1, v1, i1, v2, i2);
            ins2(w2, j2, v1, i1, v2, i2);
        }
        if (tg == 0) {
            int rloc = wm * 64 + (s >> 1) * 16 + (s & 1) * 8 + g;
            sred_v[(wn * 128 + rloc) * 2 + 0] = v1;
            sred_v[(wn * 128 + rloc) * 2 + 1] = v2;
            sred_i[(wn * 128 + rloc) * 2 + 0] = i1;
            sred_i[(wn * 128 + rloc) * 2 + 1] = i2;
        }
    }
    __syncthreads();
    if (tid < 128) {
        int row = tid;
        float v[3] = {FINF, FINF, FINF};
        int id[3] = {IINF, IINF, IINF};
#pragma unroll
        for (int w = 0; w < 4; w++) {
#pragma unroll
            for (int j = 0; j < 2; j++) {
                float x = sred_v[(w * 128 + row) * 2 + j];
                int ix = sred_i[(w * 128 + row) * 2 + j];
                if (x < v[0] || (x == v[0] && ix < id[0])) {
                    v[2] = v[1]; id[2] = id[1]; v[1] = v[0]; id[1] = id[0]; v[0] = x; id[0] = ix;
                } else if (x < v[1] || (x == v[1] && ix < id[1])) {
                    v[2] = v[1]; id[2] = id[1]; v[1] = x; id[1] = ix;
                } else if (x < v[2] || (x == v[2] && ix < id[2])) {
                    v[2] = x; id[2] = ix;
                }
            }
        }
        size_t o = ((size_t)split * MMAX + row0 + row) * 3;
#pragma unroll
        for (int k = 0; k < 3; k++) { g_t3v[o + k] = v[k]; g_t3i[o + k] = id[k]; }
    }
}

// ---------------- K3a: exact fp32 refine of top-3 x NSPL candidates per row ----------------
__global__ void k3a_refine(const float* __restrict__ A, const float* __restrict__ C, int M)
{
    int r = blockIdx.x * 8 + (threadIdx.x >> 5);
    int lane = threadIdx.x & 31;
    if (r >= M) return;
    float a_reg[12];
#pragma unroll
    for (int j = 0; j < 12; j++) a_reg[j] = A[(size_t)r * DD + j * 32 + lane];
    float a2 = g_a2[r];
    float bestv = FINF;
    int besti = IINF;
#pragma unroll
    for (int s = 0; s < NSPL; s++) {
#pragma unroll
        for (int k = 0; k < 3; k++) {
            int n = g_t3i[((size_t)s * MMAX + r) * 3 + k];
            const float* cr = C + (size_t)n * DD;
            float dot = 0.f;
#pragma unroll
            for (int j = 0; j < 12; j++) dot = fmaf(a_reg[j], cr[j * 32 + lane], dot);
#pragma unroll
            for (int off = 16; off; off >>= 1) dot += __shfl_xor_sync(0xffffffffu, dot, off);
            float d = a2 + g_b2[n] - 2.f * dot;
            if (d < bestv || (d == bestv && n < besti)) { bestv = d; besti = n; }
        }
    }
    if (lane == 0) { g_rowd[r] = bestv; g_rowarg[r] = besti; }
}

// ---------------- K3b: patch scores + per-batch argmax ----------------
__global__ void k3b_scores(int P)
{
    int b = blockIdx.x;
    int tid = threadIdx.x;
    float bestv = -1.f;
    int bestm = IINF, bestnn = 0;
    for (int p = tid; p < P; p += blockDim.x) {
        int m = b * P + p;
        float sc = sqrtf(fmaxf(g_rowd[m], 0.f));
        if (sc > bestv || (sc == bestv && m < bestm)) { bestv = sc; bestm = m; bestnn = g_rowarg[m]; }
    }
    __shared__ float sv[256];
    __shared__ int sm_[256];
    __shared__ int sn[256];
    sv[tid] = bestv; sm_[tid] = bestm; sn[tid] = bestnn;
    __syncthreads();
    for (int off = 128; off; off >>= 1) {
        if (tid < off) {
            if (sv[tid + off] > sv[tid] ||
                (sv[tid + off] == sv[tid] && sm_[tid + off] < sm_[tid])) {
                sv[tid] = sv[tid + off]; sm_[tid] = sm_[tid + off]; sn[tid] = sn[tid + off];
            }
        }
        __syncthreads();
    }
    if (tid == 0) { g_score[b] = sv[0]; g_mp[b] = sm_[0]; g_nn[b] = sn[0]; }
}

// ---------------- K4: per (batch, split-of-32) local 9-NN ----------------
__global__ void k4_knn(const float* __restrict__ C, int N)
{
    int sp = blockIdx.x;
    int b = blockIdx.y;
    int tid = threadIdx.x;
    __shared__ __align__(16) float q[DD];
    __shared__ float dv[K4CH];
    __shared__ float rv[256];
    __shared__ int   rc[256];

    int nn = g_nn[b];
    for (int j = tid; j < DD; j += 256) q[j] = C[(size_t)nn * DD + j];
    __syncthreads();
    float qn = g_b2[nn];
    int n0 = sp * K4CH;
    const float4* pq = (const float4*)q;
    for (int c = tid; c < K4CH; c += 256) {
        int n = n0 + c;
        const float4* p = (const float4*)(C + (size_t)n * DD);
        float dot = 0.f;
#pragma unroll 8
        for (int j = 0; j < DD / 4; j++) {
            float4 a = p[j], bq = pq[j];
            dot += a.x * bq.x + a.y * bq.y + a.z * bq.z + a.w * bq.w;
        }
        dv[c] = fmaxf(qn + g_b2[n] - 2.f * dot, 0.f);
    }
    __syncthreads();

    for (int k = 0; k < 9; k++) {
        float v = FINF;
        int ci = IINF;
        for (int c = tid; c < K4CH; c += 256) {
            float cv = dv[c];
            if (cv < v || (cv == v && c < ci)) { v = cv; ci = c; }
        }
        rv[tid] = v; rc[tid] = ci;
        __syncthreads();
        for (int off = 128; off; off >>= 1) {
            if (tid < off) {
                if (rv[tid + off] < rv[tid] ||
                    (rv[tid + off] == rv[tid] && rc[tid + off] < rc[tid])) {
                    rv[tid] = rv[tid + off]; rc[tid] = rc[tid + off];
                }
            }
            __syncthreads();
        }
        if (tid == 0) {
            int o = (b * K4SPL + sp) * 9 + k;
            g_knn_v[o] = rv[0];
            g_knn_i[o] = n0 + rc[0];
            dv[rc[0]] = FINF;
        }
        __syncthreads();
    }
}

// ---------------- K5: merge candidates, d_sup, softmax weight ----------------
__global__ void k5_final(const float* __restrict__ A, const float* __restrict__ C,
                         float* __restrict__ out)
{
    int b = blockIdx.x;
    int lane = threadIdx.x;
    float lv[9];
    int ln[9];
#pragma unroll
    for (int t = 0; t < 9; t++) {
        int i = lane + 32 * t;
        lv[t] = g_knn_v[b * NCAND + i];
        ln[t] = g_knn_i[b * NCAND + i];
    }
    int sup[9];
    for (int k = 0; k < 9; k++) {
        float v = FINF;
        int nix = IINF;
#pragma unroll
        for (int t = 0; t < 9; t++)
            if (lv[t] < v || (lv[t] == v && ln[t] < nix)) { v = lv[t]; nix = ln[t]; }
#pragma unroll
        for (int off = 16; off; off >>= 1) {
            float ov = __shfl_xor_sync(0xffffffffu, v, off);
            int   oi = __shfl_xor_sync(0xffffffffu, nix, off);
            if (ov < v || (ov == v && oi < nix)) { v = ov; nix = oi; }
        }
        sup[k] = nix;
#pragma unroll
        for (int t = 0; t < 9; t++)
            if (ln[t] == nix) lv[t] = FINF;
    }

    int mp = g_mp[b];
    float a2m = g_a2[mp];
    const float4* fq = (const float4*)(A + (size_t)mp * DD);
    float dsup[9];
    for (int k = 0; k < 9; k++) {
        const float4* fc = (const float4*)(C + (size_t)sup[k] * DD);
        float dot = 0.f;
        for (int j = lane; j < DD / 4; j += 32) {
            float4 x = fq[j], y = fc[j];
            dot += x.x * y.x + x.y * y.y + x.z * y.z + x.w * y.w;
        }
#pragma unroll
        for (int off = 16; off; off >>= 1) dot += __shfl_xor_sync(0xffffffffu, dot, off);
        dsup[k] = sqrtf(fmaxf(a2m + g_b2[sup[k]] - 2.f * dot, 0.f));
    }
    float mx = dsup[0];
#pragma unroll
    for (int k = 1; k < 9; k++) mx = fmaxf(mx, dsup[k]);
    float s = 0.f;
#pragma unroll
    for (int k = 0; k < 9; k++) s += expf(dsup[k] - mx);
    float w = 1.f - expf(dsup[0] - mx) / s;
    if (lane == 0) out[b] = w * g_score[b];
}

// ---------------- launch ----------------
extern "C" void kernel_launch(void* const* d_in, const int* in_sizes, int n_in,
                              void* d_out, int out_size)
{
    const float* A = (const float*)d_in[0];  // embedding [M, 384]
    const float* C = (const float*)d_in[1];  // coreset   [N, 384]
    float* out = (float*)d_out;

    int M = in_sizes[0] / DD;   // 6272
    int N = in_sizes[1] / DD;   // 16384
    int B = out_size;           // 8
    int P = M / B;              // 784

    {   // K0: bf16-hi staging (chunk-planar, pre-swizzled)
        int tot = (M + N) * 96;
        int blocks = (tot + 255) / 256;
        k0_stage<<<blocks, 256>>>(A, C, M, N);
    }
    {   // K1: norms
        int warps = M + N;
        int blocks = (warps * 32 + 255) / 256;
        k1_norms<<<blocks, 256>>>(A, C, M, N);
    }
    {   // K2: 2-CTA/SM bf16 HMMA distance-min GEMM
        cudaFuncSetAttribute(k2_mm, cudaFuncAttributeMaxDynamicSharedMemorySize, SMEM_TOTAL);
        dim3 grid(M / MT, NSPL);
        k2_mm<<<grid, 256, SMEM_TOTAL>>>(M);
    }
    k3a_refine<<<M / 8, 256>>>(A, C, M);
    k3b_scores<<<B, 256>>>(P);
    {
        dim3 grid(K4SPL, B);
        k4_knn<<<grid, 256>>>(C, N);
    }
    k5_final<<<B, 32>>>(A, C, out);
}